// round 3
// baseline (speedup 1.0000x reference)
#include <cuda_runtime.h>
#include <cstdint>

#define B 512
#define V 6890
#define NJ 24
#define NP 207
#define NJO 19
#define KTOT 217            // 207 pose-feature rows + 10 beta rows
#define VC (V*3)            // 20670

#define VERT_OFF 0
#define JNT_OFF  (B*V*3)              // 10583040
#define ROT_OFF  (JNT_OFF + B*NJO*3)  // 10612224

__constant__ int c_parents[NJ] = {0,0,0,0,1,2,3,4,5,6,7,8,9,9,9,12,13,14,16,17,18,19,20,21};

// Scratch (allocation-free rule: __device__ globals)
__device__ float g_pft[224*512];   // [k][b] transposed pose-feature(207)+beta(10), rows 217..223 unused
__device__ float g_Jdirs[11*NJ*3]; // k=0..9 shape dirs regressed to joints, k=10 template joints
__device__ float g_A[B*NJ*12];     // relative transforms, rows 3x4 row-major per joint

// ---------------------------------------------------------------------------
// K1: Rodrigues -> rot output + pose_feature (transposed) + beta rows of g_pft
// ---------------------------------------------------------------------------
__global__ void k1_rodrigues(const float* __restrict__ inputs, float* __restrict__ out) {
    int g = blockIdx.x * blockDim.x + threadIdx.x;   // g = j*512 + b
    if (g >= NJ * B) return;
    int j = g / B;
    int b = g % B;
    float rx = inputs[b*82 + j*3 + 0];
    float ry = inputs[b*82 + j*3 + 1];
    float rz = inputs[b*82 + j*3 + 2];
    float ax = rx + 1e-8f, ay = ry + 1e-8f, az = rz + 1e-8f;
    float angle = sqrtf(ax*ax + ay*ay + az*az);
    float inv = 1.0f / angle;
    float nx = rx*inv, ny = ry*inv, nz = rz*inv;
    float c = cosf(angle), s = sinf(angle), oc = 1.0f - c;
    float R[9];
    R[0] = c + oc*nx*nx;   R[1] = oc*nx*ny - s*nz; R[2] = oc*nx*nz + s*ny;
    R[3] = oc*ny*nx + s*nz; R[4] = c + oc*ny*ny;   R[5] = oc*ny*nz - s*nx;
    R[6] = oc*nz*nx - s*ny; R[7] = oc*nz*ny + s*nx; R[8] = c + oc*nz*nz;
    float* ro = out + ROT_OFF + (size_t)b*216 + j*9;
#pragma unroll
    for (int m = 0; m < 9; m++) ro[m] = R[m];
    if (j > 0) {
        int base = (j-1)*9;
#pragma unroll
        for (int m = 0; m < 9; m++) {
            float idm = (m == 0 || m == 4 || m == 8) ? 1.0f : 0.0f;
            g_pft[(base + m)*B + b] = R[m] - idm;
        }
    } else {
#pragma unroll
        for (int k = 0; k < 10; k++)
            g_pft[(NP + k)*B + b] = inputs[b*82 + 72 + k];
    }
}

// ---------------------------------------------------------------------------
// K2: Jdirs[k][j][c]: shape basis (and template) regressed to joints
// ---------------------------------------------------------------------------
__global__ void k2_jdirs(const float* __restrict__ v_template,
                         const float* __restrict__ shapes,
                         const float* __restrict__ smpl_reg) {
    int wid = (blockIdx.x * blockDim.x + threadIdx.x) >> 5;
    int lane = threadIdx.x & 31;
    if (wid >= 11*NJ*3) return;
    int k = wid / (NJ*3);
    int rem = wid % (NJ*3);
    int j = rem / 3, c = rem % 3;
    const float* src = (k < 10) ? (shapes + (size_t)k*VC) : v_template;
    float acc = 0.0f;
    for (int v = lane; v < V; v += 32)
        acc += src[v*3 + c] * smpl_reg[v*NJ + j];
#pragma unroll
    for (int o = 16; o > 0; o >>= 1) acc += __shfl_down_sync(0xffffffffu, acc, o);
    if (lane == 0) g_Jdirs[k*(NJ*3) + rem] = acc;
}

// ---------------------------------------------------------------------------
// K3: per-batch joints + kinematic chain -> g_A (3x4 relative transforms)
// one thread per batch; chain state in smem
// ---------------------------------------------------------------------------
__global__ void k3_chain(const float* __restrict__ inputs, const float* __restrict__ out) {
    __shared__ float sJ[32*NJ*3];     // joints per thread
    __shared__ float sAw[32*NJ*12];   // world transforms [R 9][t 3]
    int t = threadIdx.x;
    int b = blockIdx.x * 32 + t;
    if (b >= B) return;
    float beta[10];
#pragma unroll
    for (int k = 0; k < 10; k++) beta[k] = inputs[b*82 + 72 + k];
    float* J = sJ + t*NJ*3;
    for (int e = 0; e < NJ*3; e++) {
        float a = g_Jdirs[10*(NJ*3) + e];
#pragma unroll
        for (int k = 0; k < 10; k++) a += beta[k]*g_Jdirs[k*(NJ*3) + e];
        J[e] = a;
    }
    const float* rot = out + ROT_OFF + (size_t)b*216;
    float* Aw = sAw + t*NJ*12;
    // joint 0
#pragma unroll
    for (int m = 0; m < 9; m++) Aw[m] = rot[m];
    Aw[9] = J[0]; Aw[10] = J[1]; Aw[11] = J[2];
    for (int j = 1; j < NJ; j++) {
        int p = c_parents[j];
        const float* Rp = Aw + p*12;
        const float* Rl = rot + j*9;
        float* Wj = Aw + j*12;
        // Rw = Rp * Rl
#pragma unroll
        for (int r = 0; r < 3; r++)
#pragma unroll
            for (int cc = 0; cc < 3; cc++)
                Wj[r*3+cc] = Rp[r*3+0]*Rl[0*3+cc] + Rp[r*3+1]*Rl[1*3+cc] + Rp[r*3+2]*Rl[2*3+cc];
        float dx = J[j*3+0]-J[p*3+0], dy = J[j*3+1]-J[p*3+1], dz = J[j*3+2]-J[p*3+2];
#pragma unroll
        for (int r = 0; r < 3; r++)
            Wj[9+r] = Rp[r*3+0]*dx + Rp[r*3+1]*dy + Rp[r*3+2]*dz + Rp[9+r];
    }
    // relative: t_rel = t_world - Rw * J[j]; store rows 3x4
    float* Ab = g_A + (size_t)b*NJ*12;
    for (int j = 0; j < NJ; j++) {
        const float* Wj = Aw + j*12;
        float jx = J[j*3+0], jy = J[j*3+1], jz = J[j*3+2];
#pragma unroll
        for (int r = 0; r < 3; r++) {
            Ab[j*12 + r*4 + 0] = Wj[r*3+0];
            Ab[j*12 + r*4 + 1] = Wj[r*3+1];
            Ab[j*12 + r*4 + 2] = Wj[r*3+2];
            Ab[j*12 + r*4 + 3] = Wj[9+r] - (Wj[r*3+0]*jx + Wj[r*3+1]*jy + Wj[r*3+2]*jz);
        }
    }
}

// ---------------------------------------------------------------------------
// K4: fused GEMM (v_posed) + skinning -> vertices
// tile: 64 vertices (192 cols) x 32 batches, 256 threads, each 2b x 4v
// ---------------------------------------------------------------------------
#define TV 64
#define TB 32
#define KC 8
#define KCHUNKS 28   // 28*8 = 224 >= 217

__global__ __launch_bounds__(256) void k4_gemm_skin(
    const float* __restrict__ posedirs, const float* __restrict__ shapes,
    const float* __restrict__ v_template, const float* __restrict__ lbs,
    float* __restrict__ out)
{
    __shared__ float smem[10752]; // mainloop: sP 1536 + sPF 256 ; epilogue: sA 9216 + sW 1536
    float* sP  = smem;
    float* sPF = smem + 1536;
    float* sA  = smem;
    float* sW  = smem + TB*NJ*12; // 9216

    int tid = threadIdx.x;
    int tx = tid & 15;      // vertex quad 0..15
    int ty = tid >> 4;      // batch pair 0..15
    int v0 = blockIdx.x * TV;
    int b0 = blockIdx.y * TB;

    float acc[2][12];
#pragma unroll
    for (int bi = 0; bi < 2; bi++)
#pragma unroll
        for (int e = 0; e < 12; e++) acc[bi][e] = 0.0f;

    for (int kc = 0; kc < KCHUNKS; kc++) {
        // stage P chunk (KC x 192)
        for (int i = tid; i < KC*192; i += 256) {
            int kk = i / 192, col = i % 192;
            int k = kc*KC + kk;
            int gc = v0*3 + col;
            float val = 0.0f;
            if (gc < VC) {
                if (k < NP) val = posedirs[(size_t)k*VC + gc];
                else if (k < KTOT) val = shapes[(size_t)(k-NP)*VC + gc];
            }
            sP[i] = val;
        }
        // stage PF chunk (KC x 32)
        for (int i = tid; i < KC*TB; i += 256) {
            int kk = i / TB, bb = i % TB;
            int k = kc*KC + kk;
            sPF[i] = (k < KTOT) ? g_pft[k*B + b0 + bb] : 0.0f;
        }
        __syncthreads();
#pragma unroll
        for (int kk = 0; kk < KC; kk++) {
            float p[12];
            *(float4*)&p[0] = *(float4*)&sP[kk*192 + tx*12];
            *(float4*)&p[4] = *(float4*)&sP[kk*192 + tx*12 + 4];
            *(float4*)&p[8] = *(float4*)&sP[kk*192 + tx*12 + 8];
            float f0 = sPF[kk*TB + ty*2];
            float f1 = sPF[kk*TB + ty*2 + 1];
#pragma unroll
            for (int e = 0; e < 12; e++) {
                acc[0][e] += f0 * p[e];
                acc[1][e] += f1 * p[e];
            }
        }
        __syncthreads();
    }

    // template add
    float tmpl[12];
#pragma unroll
    for (int vi = 0; vi < 4; vi++) {
        int v = v0 + tx*4 + vi;
#pragma unroll
        for (int c = 0; c < 3; c++)
            tmpl[vi*3+c] = (v < V) ? v_template[v*3+c] : 0.0f;
    }

    // stage A (32 batches x 24 x 12) and W (64 verts x 24)
    for (int i = tid; i < TB*NJ*12; i += 256) sA[i] = g_A[(size_t)b0*NJ*12 + i];
    for (int i = tid; i < TV*NJ; i += 256) {
        int gi = v0*NJ + i;
        sW[i] = (gi < V*NJ) ? lbs[gi] : 0.0f;
    }
    __syncthreads();

#pragma unroll
    for (int vi = 0; vi < 4; vi++) {
        int vloc = tx*4 + vi;
        int v = v0 + vloc;
        float w[NJ];
#pragma unroll
        for (int q = 0; q < 6; q++)
            *(float4*)&w[q*4] = *(float4*)&sW[vloc*NJ + q*4];
#pragma unroll
        for (int bi = 0; bi < 2; bi++) {
            int bloc = ty*2 + bi;
            float vx = acc[bi][vi*3+0] + tmpl[vi*3+0];
            float vy = acc[bi][vi*3+1] + tmpl[vi*3+1];
            float vz = acc[bi][vi*3+2] + tmpl[vi*3+2];
            float T[12];
#pragma unroll
            for (int e = 0; e < 12; e++) T[e] = 0.0f;
#pragma unroll
            for (int j = 0; j < NJ; j++) {
                float wj = w[j];
                float4 a0 = *(float4*)&sA[bloc*NJ*12 + j*12 + 0];
                float4 a1 = *(float4*)&sA[bloc*NJ*12 + j*12 + 4];
                float4 a2 = *(float4*)&sA[bloc*NJ*12 + j*12 + 8];
                T[0] += wj*a0.x; T[1] += wj*a0.y; T[2]  += wj*a0.z; T[3]  += wj*a0.w;
                T[4] += wj*a1.x; T[5] += wj*a1.y; T[6]  += wj*a1.z; T[7]  += wj*a1.w;
                T[8] += wj*a2.x; T[9] += wj*a2.y; T[10] += wj*a2.z; T[11] += wj*a2.w;
            }
            if (v < V) {
                int b = b0 + bloc;
                float* o = out + VERT_OFF + ((size_t)b*V + v)*3;
                o[0] = T[0]*vx + T[1]*vy + T[2]*vz  + T[3];
                o[1] = T[4]*vx + T[5]*vy + T[6]*vz  + T[7];
                o[2] = T[8]*vx + T[9]*vy + T[10]*vz + T[11];
            }
        }
    }
}

// ---------------------------------------------------------------------------
// K5: joints = regressor^T @ vertices  — one block per batch, vertices read once
// ---------------------------------------------------------------------------
__global__ __launch_bounds__(256) void k5_joints(const float* __restrict__ jreg,
                                                 float* __restrict__ out)
{
    __shared__ float sreg[256*NJO];  // 19456 B
    int b = blockIdx.x;
    int tid = threadIdx.x;
    const float* verts = out + VERT_OFF + (size_t)b*V*3;
    float acc[NJO*3];
#pragma unroll
    for (int e = 0; e < NJO*3; e++) acc[e] = 0.0f;

    for (int base = 0; base < V; base += 256) {
        for (int i = tid; i < 256*NJO; i += 256) {
            int row = base + i / NJO;
            sreg[i] = (row < V) ? jreg[row*NJO + (i % NJO)] : 0.0f;
        }
        __syncthreads();
        int v = base + tid;
        if (v < V) {
            float px = verts[v*3+0], py = verts[v*3+1], pz = verts[v*3+2];
#pragma unroll
            for (int j = 0; j < NJO; j++) {
                float r = sreg[tid*NJO + j];
                acc[j*3+0] += r*px;
                acc[j*3+1] += r*py;
                acc[j*3+2] += r*pz;
            }
        }
        __syncthreads();
    }
    // warp reduce
#pragma unroll
    for (int e = 0; e < NJO*3; e++) {
#pragma unroll
        for (int o = 16; o > 0; o >>= 1)
            acc[e] += __shfl_down_sync(0xffffffffu, acc[e], o);
    }
    int warp = tid >> 5, lane = tid & 31;
    float* spart = sreg;  // reuse: 8 warps x 57
    if (lane == 0) {
#pragma unroll
        for (int e = 0; e < NJO*3; e++) spart[warp*(NJO*3) + e] = acc[e];
    }
    __syncthreads();
    if (tid < NJO*3) {
        float s = 0.0f;
#pragma unroll
        for (int w = 0; w < 8; w++) s += spart[w*(NJO*3) + tid];
        out[JNT_OFF + b*(NJO*3) + tid] = s;
    }
}

// ---------------------------------------------------------------------------
extern "C" void kernel_launch(void* const* d_in, const int* in_sizes, int n_in,
                              void* d_out, int out_size) {
    const float* inputs     = (const float*)d_in[0];
    const float* v_template = (const float*)d_in[1];
    const float* shapes     = (const float*)d_in[2];
    const float* posedirs   = (const float*)d_in[3];
    const float* smpl_reg   = (const float*)d_in[4];
    const float* lbs        = (const float*)d_in[5];
    const float* jreg       = (const float*)d_in[6];
    float* out = (float*)d_out;

    k1_rodrigues<<<(NJ*B + 255)/256, 256>>>(inputs, out);
    k2_jdirs<<<(11*NJ*3*32 + 255)/256, 256>>>(v_template, shapes, smpl_reg);
    k3_chain<<<B/32, 32>>>(inputs, out);
    dim3 g4((V + TV - 1)/TV, B/TB);
    k4_gemm_skin<<<g4, 256>>>(posedirs, shapes, v_template, lbs, out);
    k5_joints<<<B, 256>>>(jreg, out);
}

// round 4
// speedup vs baseline: 2.5828x; 2.5828x over previous
#include <cuda_runtime.h>
#include <cstdint>

#define B 512
#define V 6890
#define NJ 24
#define NP 207
#define NJO 19
#define VC (V*3)            // 20670
#define VCP 20736           // padded vc stride = 162*128

#define VERT_OFF 0
#define JNT_OFF  (B*V*3)              // 10583040
#define ROT_OFF  (JNT_OFF + B*NJO*3)  // 10612224

typedef unsigned long long ull;

__constant__ int c_parents[NJ] = {0,0,0,0,1,2,3,4,5,6,7,8,9,9,9,12,13,14,16,17,18,19,20,21};

// Scratch (__device__ globals: allocation-free rule)
__device__ float g_pft[224*512];        // [k][b]: 207 pose-feat + 10 beta + row217=1.0 (+zeros)
__device__ float g_Jdirs[11*NJ*3];
__device__ float g_A[B*NJ*12];          // relative transforms 3x4 row-major
__device__ float g_vposed[(size_t)B*VCP]; // ~42.5 MB scratch: v_posed incl. template

// ---- packed f32x2 helpers --------------------------------------------------
__device__ __forceinline__ void ffma2(ull &d, ull a, ull b) {
    asm("fma.rn.f32x2 %0, %1, %2, %0;" : "+l"(d) : "l"(a), "l"(b));
}
__device__ __forceinline__ ull pack2(float x, float y) {
    ull r; asm("mov.b64 %0, {%1, %2};" : "=l"(r) : "f"(x), "f"(y)); return r;
}
__device__ __forceinline__ void unpack2(ull v, float &lo, float &hi) {
    asm("mov.b64 {%0, %1}, %2;" : "=f"(lo), "=f"(hi) : "l"(v));
}

// ---------------------------------------------------------------------------
// K1: Rodrigues -> rot output + transposed pose-feature / beta / template-coef
// ---------------------------------------------------------------------------
__global__ void k1_rodrigues(const float* __restrict__ inputs, float* __restrict__ out) {
    int g = blockIdx.x * blockDim.x + threadIdx.x;
    if (g >= NJ * B) return;
    int j = g / B;
    int b = g % B;
    float rx = inputs[b*82 + j*3 + 0];
    float ry = inputs[b*82 + j*3 + 1];
    float rz = inputs[b*82 + j*3 + 2];
    float ax = rx + 1e-8f, ay = ry + 1e-8f, az = rz + 1e-8f;
    float angle = sqrtf(ax*ax + ay*ay + az*az);
    float inv = 1.0f / angle;
    float nx = rx*inv, ny = ry*inv, nz = rz*inv;
    float c = cosf(angle), s = sinf(angle), oc = 1.0f - c;
    float R[9];
    R[0] = c + oc*nx*nx;    R[1] = oc*nx*ny - s*nz; R[2] = oc*nx*nz + s*ny;
    R[3] = oc*ny*nx + s*nz; R[4] = c + oc*ny*ny;    R[5] = oc*ny*nz - s*nx;
    R[6] = oc*nz*nx - s*ny; R[7] = oc*nz*ny + s*nx; R[8] = c + oc*nz*nz;
    float* ro = out + ROT_OFF + (size_t)b*216 + j*9;
#pragma unroll
    for (int m = 0; m < 9; m++) ro[m] = R[m];
    if (j > 0) {
        int base = (j-1)*9;
#pragma unroll
        for (int m = 0; m < 9; m++) {
            float idm = (m == 0 || m == 4 || m == 8) ? 1.0f : 0.0f;
            g_pft[(base + m)*B + b] = R[m] - idm;
        }
    } else {
#pragma unroll
        for (int k = 0; k < 10; k++)
            g_pft[(NP + k)*B + b] = inputs[b*82 + 72 + k];
        g_pft[217*B + b] = 1.0f;   // template coefficient
#pragma unroll
        for (int k = 218; k < 224; k++)
            g_pft[k*B + b] = 0.0f; // K padding
    }
}

// ---------------------------------------------------------------------------
// K2: Jdirs (shape basis + template regressed to joints)
// ---------------------------------------------------------------------------
__global__ void k2_jdirs(const float* __restrict__ v_template,
                         const float* __restrict__ shapes,
                         const float* __restrict__ smpl_reg) {
    int wid = (blockIdx.x * blockDim.x + threadIdx.x) >> 5;
    int lane = threadIdx.x & 31;
    if (wid >= 11*NJ*3) return;
    int k = wid / (NJ*3);
    int rem = wid % (NJ*3);
    int j = rem / 3, c = rem % 3;
    const float* src = (k < 10) ? (shapes + (size_t)k*VC) : v_template;
    float acc = 0.0f;
    for (int v = lane; v < V; v += 32)
        acc += src[v*3 + c] * smpl_reg[v*NJ + j];
#pragma unroll
    for (int o = 16; o > 0; o >>= 1) acc += __shfl_down_sync(0xffffffffu, acc, o);
    if (lane == 0) g_Jdirs[k*(NJ*3) + rem] = acc;
}

// ---------------------------------------------------------------------------
// K3: per-batch kinematic chain -> g_A
// ---------------------------------------------------------------------------
__global__ void k3_chain(const float* __restrict__ inputs, const float* __restrict__ out) {
    __shared__ float sJ[32*NJ*3];
    __shared__ float sAw[32*NJ*12];
    int t = threadIdx.x;
    int b = blockIdx.x * 32 + t;
    if (b >= B) return;
    float beta[10];
#pragma unroll
    for (int k = 0; k < 10; k++) beta[k] = inputs[b*82 + 72 + k];
    float* J = sJ + t*NJ*3;
    for (int e = 0; e < NJ*3; e++) {
        float a = g_Jdirs[10*(NJ*3) + e];
#pragma unroll
        for (int k = 0; k < 10; k++) a += beta[k]*g_Jdirs[k*(NJ*3) + e];
        J[e] = a;
    }
    const float* rot = out + ROT_OFF + (size_t)b*216;
    float* Aw = sAw + t*NJ*12;
#pragma unroll
    for (int m = 0; m < 9; m++) Aw[m] = rot[m];
    Aw[9] = J[0]; Aw[10] = J[1]; Aw[11] = J[2];
    for (int j = 1; j < NJ; j++) {
        int p = c_parents[j];
        const float* Rp = Aw + p*12;
        const float* Rl = rot + j*9;
        float* Wj = Aw + j*12;
#pragma unroll
        for (int r = 0; r < 3; r++)
#pragma unroll
            for (int cc = 0; cc < 3; cc++)
                Wj[r*3+cc] = Rp[r*3+0]*Rl[0*3+cc] + Rp[r*3+1]*Rl[1*3+cc] + Rp[r*3+2]*Rl[2*3+cc];
        float dx = J[j*3+0]-J[p*3+0], dy = J[j*3+1]-J[p*3+1], dz = J[j*3+2]-J[p*3+2];
#pragma unroll
        for (int r = 0; r < 3; r++)
            Wj[9+r] = Rp[r*3+0]*dx + Rp[r*3+1]*dy + Rp[r*3+2]*dz + Rp[9+r];
    }
    float* Ab = g_A + (size_t)b*NJ*12;
    for (int j = 0; j < NJ; j++) {
        const float* Wj = Aw + j*12;
        float jx = J[j*3+0], jy = J[j*3+1], jz = J[j*3+2];
#pragma unroll
        for (int r = 0; r < 3; r++) {
            Ab[j*12 + r*4 + 0] = Wj[r*3+0];
            Ab[j*12 + r*4 + 1] = Wj[r*3+1];
            Ab[j*12 + r*4 + 2] = Wj[r*3+2];
            Ab[j*12 + r*4 + 3] = Wj[9+r] - (Wj[r*3+0]*jx + Wj[r*3+1]*jy + Wj[r*3+2]*jz);
        }
    }
}

// ---------------------------------------------------------------------------
// K4a: v_posed GEMM  C[b][vc] = sum_k F[k][b] * P[k][vc]
//   K = 218 real (207 pose + 10 beta + 1 template), padded to 224.
//   Block tile 64b x 128vc, 256 threads, thread tile 4b x 8vc (4x4 f32x2).
// ---------------------------------------------------------------------------
#define GM 64
#define GN 128
#define GK 16

__global__ __launch_bounds__(256) void k4a_gemm(
    const float* __restrict__ posedirs, const float* __restrict__ shapes,
    const float* __restrict__ v_template)
{
    __shared__ __align__(16) float sP[GK*GN];  // 8KB
    __shared__ __align__(16) float sF[GK*GM];  // 4KB
    int tid = threadIdx.x;
    int tx = tid & 15;      // vc octet 0..15
    int ty = tid >> 4;      // b quad  0..15
    int n0 = blockIdx.x * GN;
    int b0 = blockIdx.y * GM;

    ull acc[4][4];
#pragma unroll
    for (int bi = 0; bi < 4; bi++)
#pragma unroll
        for (int ni = 0; ni < 4; ni++) acc[bi][ni] = 0ull;

    for (int kc = 0; kc < 14; kc++) {
        // stage P: 16 rows x 128 cols, float2 granularity (rows are 8B aligned)
#pragma unroll
        for (int i = tid; i < (GK*GN)/2; i += 256) {
            int row = i >> 6;
            int seg = i & 63;
            int k = kc*GK + row;
            int gc = n0 + seg*2;
            float2 val = make_float2(0.f, 0.f);
            const float* src = nullptr;
            if (k < NP)        src = posedirs + (size_t)k*VC;
            else if (k < 217)  src = shapes + (size_t)(k-NP)*VC;
            else if (k == 217) src = v_template;
            if (src && gc < VC) val = *(const float2*)(src + gc);
            *(float2*)&sP[row*GN + seg*2] = val;
        }
        // stage F: 16 rows x 64 cols, one float4 per thread
        {
            int row = tid >> 4;
            int seg = tid & 15;
            int k = kc*GK + row;
            *(float4*)&sF[row*GM + seg*4] = *(const float4*)&g_pft[k*B + b0 + seg*4];
        }
        __syncthreads();
#pragma unroll
        for (int kk = 0; kk < GK; kk++) {
            ulonglong2 pa = *(ulonglong2*)&sP[kk*GN + tx*8];
            ulonglong2 pb = *(ulonglong2*)&sP[kk*GN + tx*8 + 4];
            ull a0 = pa.x, a1 = pa.y, a2 = pb.x, a3 = pb.y;
            float4 f = *(float4*)&sF[kk*GM + ty*4];
            ull f0 = pack2(f.x, f.x);
            ull f1 = pack2(f.y, f.y);
            ull f2 = pack2(f.z, f.z);
            ull f3 = pack2(f.w, f.w);
            ffma2(acc[0][0], f0, a0); ffma2(acc[0][1], f0, a1);
            ffma2(acc[0][2], f0, a2); ffma2(acc[0][3], f0, a3);
            ffma2(acc[1][0], f1, a0); ffma2(acc[1][1], f1, a1);
            ffma2(acc[1][2], f1, a2); ffma2(acc[1][3], f1, a3);
            ffma2(acc[2][0], f2, a0); ffma2(acc[2][1], f2, a1);
            ffma2(acc[2][2], f2, a2); ffma2(acc[2][3], f2, a3);
            ffma2(acc[3][0], f3, a0); ffma2(acc[3][1], f3, a1);
            ffma2(acc[3][2], f3, a2); ffma2(acc[3][3], f3, a3);
        }
        __syncthreads();
    }
#pragma unroll
    for (int bi = 0; bi < 4; bi++) {
        float* dst = &g_vposed[(size_t)(b0 + ty*4 + bi)*VCP + n0 + tx*8];
        ulonglong2 s0; s0.x = acc[bi][0]; s0.y = acc[bi][1];
        *(ulonglong2*)dst = s0;
        ulonglong2 s1; s1.x = acc[bi][2]; s1.y = acc[bi][3];
        *(ulonglong2*)(dst + 4) = s1;
    }
}

// ---------------------------------------------------------------------------
// K4b: skinning. Block tile: 16 batches (8 f32x2 pairs) x 64 verts.
//   256 threads = 8 pairs x 32 vlanes; each thread: 1 pair x 2 verts.
//   A staged pair-interleaved (warp-broadcast LDS.128), W padded stride 25.
// ---------------------------------------------------------------------------
#define ST_VT 64
#define ST_BT 16

__global__ __launch_bounds__(256) void k4b_skin(
    const float* __restrict__ lbs, float* __restrict__ out)
{
    __shared__ __align__(16) float sA2[8*288*2];  // 18KB: ((p*288 + r)*2 + h)
    __shared__ float sW[ST_VT*25];                 // stride 25: conflict-free
    int tid = threadIdx.x;
    int v0 = blockIdx.x * ST_VT;
    int b0 = blockIdx.y * ST_BT;

    for (int i = tid; i < 8*2*288; i += 256) {
        int p = i / 576; int rem = i % 576; int h = rem / 288; int r = rem % 288;
        sA2[(p*288 + r)*2 + h] = g_A[(size_t)(b0 + 2*p + h)*288 + r];
    }
    for (int i = tid; i < ST_VT*NJ; i += 256) {
        int vl = i / NJ; int j = i % NJ;
        int v = v0 + vl;
        sW[vl*25 + j] = (v < V) ? lbs[v*NJ + j] : 0.0f;
    }
    __syncthreads();

    int p  = tid >> 5;   // whole warp shares one batch pair -> sA2 broadcast
    int vt = tid & 31;

    ull T[2][12];
#pragma unroll
    for (int vi = 0; vi < 2; vi++)
#pragma unroll
        for (int e = 0; e < 12; e++) T[vi][e] = 0ull;

    const float* Ap = sA2 + p*576;
#pragma unroll
    for (int j = 0; j < NJ; j++) {
        ull a[12];
#pragma unroll
        for (int e2 = 0; e2 < 6; e2++) {
            ulonglong2 t = *(ulonglong2*)&Ap[(j*12 + e2*2)*2];
            a[e2*2] = t.x; a[e2*2+1] = t.y;
        }
#pragma unroll
        for (int vi = 0; vi < 2; vi++) {
            float w = sW[(vt + vi*32)*25 + j];
            ull ww = pack2(w, w);
#pragma unroll
            for (int e = 0; e < 12; e++) ffma2(T[vi][e], ww, a[e]);
        }
    }

#pragma unroll
    for (int vi = 0; vi < 2; vi++) {
        int v = v0 + vt + vi*32;
        if (v >= V) continue;
        float Ta[12], Tb[12];
#pragma unroll
        for (int e = 0; e < 12; e++) unpack2(T[vi][e], Ta[e], Tb[e]);
        {
            int b = b0 + 2*p;
            const float* hp = &g_vposed[(size_t)b*VCP + v*3];
            float vx = hp[0], vy = hp[1], vz = hp[2];
            float* o = out + VERT_OFF + ((size_t)b*V + v)*3;
            o[0] = Ta[0]*vx + Ta[1]*vy + Ta[2]*vz  + Ta[3];
            o[1] = Ta[4]*vx + Ta[5]*vy + Ta[6]*vz  + Ta[7];
            o[2] = Ta[8]*vx + Ta[9]*vy + Ta[10]*vz + Ta[11];
        }
        {
            int b = b0 + 2*p + 1;
            const float* hp = &g_vposed[(size_t)b*VCP + v*3];
            float vx = hp[0], vy = hp[1], vz = hp[2];
            float* o = out + VERT_OFF + ((size_t)b*V + v)*3;
            o[0] = Tb[0]*vx + Tb[1]*vy + Tb[2]*vz  + Tb[3];
            o[1] = Tb[4]*vx + Tb[5]*vy + Tb[6]*vz  + Tb[7];
            o[2] = Tb[8]*vx + Tb[9]*vy + Tb[10]*vz + Tb[11];
        }
    }
}

// ---------------------------------------------------------------------------
// K5: joints = regressor^T @ vertices — one block per batch
// ---------------------------------------------------------------------------
__global__ __launch_bounds__(256) void k5_joints(const float* __restrict__ jreg,
                                                 float* __restrict__ out)
{
    __shared__ float sreg[256*NJO];
    int b = blockIdx.x;
    int tid = threadIdx.x;
    const float* verts = out + VERT_OFF + (size_t)b*V*3;
    float acc[NJO*3];
#pragma unroll
    for (int e = 0; e < NJO*3; e++) acc[e] = 0.0f;

    for (int base = 0; base < V; base += 256) {
        for (int i = tid; i < 256*NJO; i += 256) {
            int row = base + i / NJO;
            sreg[i] = (row < V) ? jreg[row*NJO + (i % NJO)] : 0.0f;
        }
        __syncthreads();
        int v = base + tid;
        if (v < V) {
            float px = verts[v*3+0], py = verts[v*3+1], pz = verts[v*3+2];
#pragma unroll
            for (int j = 0; j < NJO; j++) {
                float r = sreg[tid*NJO + j];
                acc[j*3+0] += r*px;
                acc[j*3+1] += r*py;
                acc[j*3+2] += r*pz;
            }
        }
        __syncthreads();
    }
#pragma unroll
    for (int e = 0; e < NJO*3; e++) {
#pragma unroll
        for (int o = 16; o > 0; o >>= 1)
            acc[e] += __shfl_down_sync(0xffffffffu, acc[e], o);
    }
    int warp = tid >> 5, lane = tid & 31;
    float* spart = sreg;
    if (lane == 0) {
#pragma unroll
        for (int e = 0; e < NJO*3; e++) spart[warp*(NJO*3) + e] = acc[e];
    }
    __syncthreads();
    if (tid < NJO*3) {
        float s = 0.0f;
#pragma unroll
        for (int w = 0; w < 8; w++) s += spart[w*(NJO*3) + tid];
        out[JNT_OFF + b*(NJO*3) + tid] = s;
    }
}

// ---------------------------------------------------------------------------
extern "C" void kernel_launch(void* const* d_in, const int* in_sizes, int n_in,
                              void* d_out, int out_size) {
    const float* inputs     = (const float*)d_in[0];
    const float* v_template = (const float*)d_in[1];
    const float* shapes     = (const float*)d_in[2];
    const float* posedirs   = (const float*)d_in[3];
    const float* smpl_reg   = (const float*)d_in[4];
    const float* lbs        = (const float*)d_in[5];
    const float* jreg       = (const float*)d_in[6];
    float* out = (float*)d_out;

    k1_rodrigues<<<(NJ*B + 255)/256, 256>>>(inputs, out);
    k2_jdirs<<<(11*NJ*3*32 + 255)/256, 256>>>(v_template, shapes, smpl_reg);
    k3_chain<<<B/32, 32>>>(inputs, out);
    dim3 ga(VCP/GN, B/GM);           // (162, 8)
    k4a_gemm<<<ga, 256>>>(posedirs, shapes, v_template);
    dim3 gb((V + ST_VT - 1)/ST_VT, B/ST_BT);  // (108, 32)
    k4b_skin<<<gb, 256>>>(lbs, out);
    k5_joints<<<B, 256>>>(jreg, out);
}

// round 8
// speedup vs baseline: 2.9236x; 1.1319x over previous
#include <cuda_runtime.h>
#include <cstdint>

#define B 512
#define V 6890
#define NJ 24
#define NP 207
#define NJO 19
#define VC (V*3)            // 20670
#define VCP 20736           // padded vc stride = 162*128
#define KP 224              // padded K (218 real rows)

#define VERT_OFF 0
#define JNT_OFF  (B*V*3)              // 10583040
#define ROT_OFF  (JNT_OFF + B*NJO*3)  // 10612224

typedef unsigned long long ull;

__constant__ int c_parents[NJ] = {0,0,0,0,1,2,3,4,5,6,7,8,9,9,9,12,13,14,16,17,18,19,20,21};

// Scratch (__device__ globals: allocation-free rule)
__device__ float g_P[(size_t)KP*VCP];     // 18.6MB packed+padded [posedirs;shapes;template;0]
__device__ float g_pft2[KP*1024];         // [k][b*2+{0,1}] duplicated factor matrix
__device__ float g_Jdirs[11*NJ*3];
__device__ float g_A[B*NJ*12];            // relative transforms 3x4 row-major
__device__ float g_vposed[(size_t)B*VCP]; // 42.5MB v_posed (incl template)

// ---- packed f32x2 helpers --------------------------------------------------
__device__ __forceinline__ void ffma2(ull &d, ull a, ull b) {
    asm("fma.rn.f32x2 %0, %1, %2, %0;" : "+l"(d) : "l"(a), "l"(b));
}
__device__ __forceinline__ ull pack2(float x, float y) {
    ull r; asm("mov.b64 %0, {%1, %2};" : "=l"(r) : "f"(x), "f"(y)); return r;
}
__device__ __forceinline__ void unpack2(ull v, float &lo, float &hi) {
    asm("mov.b64 {%0, %1}, %2;" : "=f"(lo), "=f"(hi) : "l"(v));
}
__device__ __forceinline__ void cpasync16(uint32_t s, const void* g) {
    asm volatile("cp.async.cg.shared.global [%0], [%1], 16;" :: "r"(s), "l"(g));
}

// ---------------------------------------------------------------------------
// K0: pack P = [posedirs; shapes; v_template; zeros] into padded g_P
// ---------------------------------------------------------------------------
__global__ void k0_pack(const float* __restrict__ posedirs,
                        const float* __restrict__ shapes,
                        const float* __restrict__ v_template) {
    int idx = blockIdx.x * blockDim.x + threadIdx.x;   // one float4 of g_P
    if (idx >= KP*(VCP/4)) return;
    int k = idx / (VCP/4);
    int q = idx % (VCP/4);
    int gc = q * 4;
    float4 val = make_float4(0.f, 0.f, 0.f, 0.f);
    if (k < 218) {
        const float* src = (k < NP) ? posedirs + (size_t)k*VC
                         : (k < 217) ? shapes + (size_t)(k-NP)*VC
                         : v_template;
        if (gc + 3 < VC) {
            float2 u = *(const float2*)(src + gc);
            float2 w = *(const float2*)(src + gc + 2);
            val.x = u.x; val.y = u.y; val.z = w.x; val.w = w.y;
        } else {
            if (gc + 0 < VC) val.x = src[gc + 0];
            if (gc + 1 < VC) val.y = src[gc + 1];
            if (gc + 2 < VC) val.z = src[gc + 2];
        }
    }
    *(float4*)&g_P[(size_t)k*VCP + gc] = val;
}

// ---------------------------------------------------------------------------
// K1: Rodrigues -> rot output + duplicated factor matrix g_pft2
// ---------------------------------------------------------------------------
__global__ void k1_rodrigues(const float* __restrict__ inputs, float* __restrict__ out) {
    int g = blockIdx.x * blockDim.x + threadIdx.x;
    if (g >= NJ * B) return;
    int j = g / B;
    int b = g % B;
    float rx = inputs[b*82 + j*3 + 0];
    float ry = inputs[b*82 + j*3 + 1];
    float rz = inputs[b*82 + j*3 + 2];
    float ax = rx + 1e-8f, ay = ry + 1e-8f, az = rz + 1e-8f;
    float angle = sqrtf(ax*ax + ay*ay + az*az);
    float inv = 1.0f / angle;
    float nx = rx*inv, ny = ry*inv, nz = rz*inv;
    float c = cosf(angle), s = sinf(angle), oc = 1.0f - c;
    float R[9];
    R[0] = c + oc*nx*nx;    R[1] = oc*nx*ny - s*nz; R[2] = oc*nx*nz + s*ny;
    R[3] = oc*ny*nx + s*nz; R[4] = c + oc*ny*ny;    R[5] = oc*ny*nz - s*nx;
    R[6] = oc*nz*nx - s*ny; R[7] = oc*nz*ny + s*nx; R[8] = c + oc*nz*nz;
    float* ro = out + ROT_OFF + (size_t)b*216 + j*9;
#pragma unroll
    for (int m = 0; m < 9; m++) ro[m] = R[m];
    if (j > 0) {
        int base = (j-1)*9;
#pragma unroll
        for (int m = 0; m < 9; m++) {
            float idm = (m == 0 || m == 4 || m == 8) ? 1.0f : 0.0f;
            float val = R[m] - idm;
            g_pft2[(base + m)*1024 + b*2 + 0] = val;
            g_pft2[(base + m)*1024 + b*2 + 1] = val;
        }
    } else {
#pragma unroll
        for (int k = 0; k < 10; k++) {
            float val = inputs[b*82 + 72 + k];
            g_pft2[(NP + k)*1024 + b*2 + 0] = val;
            g_pft2[(NP + k)*1024 + b*2 + 1] = val;
        }
        g_pft2[217*1024 + b*2 + 0] = 1.0f;
        g_pft2[217*1024 + b*2 + 1] = 1.0f;
#pragma unroll
        for (int k = 218; k < KP; k++) {
            g_pft2[k*1024 + b*2 + 0] = 0.0f;
            g_pft2[k*1024 + b*2 + 1] = 0.0f;
        }
    }
}

// ---------------------------------------------------------------------------
// K2: Jdirs (shape basis + template regressed to joints) — coalesced
// one block per (k, c): 11*3 = 33 blocks
// ---------------------------------------------------------------------------
__global__ __launch_bounds__(256) void k2_jdirs(const float* __restrict__ v_template,
                         const float* __restrict__ shapes,
                         const float* __restrict__ smpl_reg) {
    __shared__ float spart[8][NJ];
    int k = blockIdx.x / 3;
    int c = blockIdx.x % 3;
    int tid = threadIdx.x;
    const float* src = (k < 10) ? (shapes + (size_t)k*VC) : v_template;
    float acc[NJ];
#pragma unroll
    for (int j = 0; j < NJ; j++) acc[j] = 0.0f;
    for (int v = tid; v < V; v += 256) {
        float sv = src[v*3 + c];
        const float4* r = (const float4*)&smpl_reg[v*NJ];
#pragma unroll
        for (int q = 0; q < 6; q++) {
            float4 rv = r[q];
            acc[q*4+0] += sv * rv.x;
            acc[q*4+1] += sv * rv.y;
            acc[q*4+2] += sv * rv.z;
            acc[q*4+3] += sv * rv.w;
        }
    }
#pragma unroll
    for (int j = 0; j < NJ; j++) {
#pragma unroll
        for (int o = 16; o > 0; o >>= 1)
            acc[j] += __shfl_down_sync(0xffffffffu, acc[j], o);
    }
    int warp = tid >> 5, lane = tid & 31;
    if (lane == 0) {
#pragma unroll
        for (int j = 0; j < NJ; j++) spart[warp][j] = acc[j];
    }
    __syncthreads();
    if (tid < NJ) {
        float s = 0.0f;
#pragma unroll
        for (int w = 0; w < 8; w++) s += spart[w][tid];
        g_Jdirs[k*(NJ*3) + tid*3 + c] = s;
    }
}

// ---------------------------------------------------------------------------
// K3: per-batch kinematic chain -> g_A
// ---------------------------------------------------------------------------
__global__ void k3_chain(const float* __restrict__ inputs, const float* __restrict__ out) {
    __shared__ float sJ[32*NJ*3];
    __shared__ float sAw[32*NJ*12];
    int t = threadIdx.x;
    int b = blockIdx.x * 32 + t;
    if (b >= B) return;
    float beta[10];
#pragma unroll
    for (int k = 0; k < 10; k++) beta[k] = inputs[b*82 + 72 + k];
    float* J = sJ + t*NJ*3;
    for (int e = 0; e < NJ*3; e++) {
        float a = g_Jdirs[10*(NJ*3) + e];
#pragma unroll
        for (int k = 0; k < 10; k++) a += beta[k]*g_Jdirs[k*(NJ*3) + e];
        J[e] = a;
    }
    const float* rot = out + ROT_OFF + (size_t)b*216;
    float* Aw = sAw + t*NJ*12;
#pragma unroll
    for (int m = 0; m < 9; m++) Aw[m] = rot[m];
    Aw[9] = J[0]; Aw[10] = J[1]; Aw[11] = J[2];
    for (int j = 1; j < NJ; j++) {
        int p = c_parents[j];
        const float* Rp = Aw + p*12;
        const float* Rl = rot + j*9;
        float* Wj = Aw + j*12;
#pragma unroll
        for (int r = 0; r < 3; r++)
#pragma unroll
            for (int cc = 0; cc < 3; cc++)
                Wj[r*3+cc] = Rp[r*3+0]*Rl[0*3+cc] + Rp[r*3+1]*Rl[1*3+cc] + Rp[r*3+2]*Rl[2*3+cc];
        float dx = J[j*3+0]-J[p*3+0], dy = J[j*3+1]-J[p*3+1], dz = J[j*3+2]-J[p*3+2];
#pragma unroll
        for (int r = 0; r < 3; r++)
            Wj[9+r] = Rp[r*3+0]*dx + Rp[r*3+1]*dy + Rp[r*3+2]*dz + Rp[9+r];
    }
    float* Ab = g_A + (size_t)b*NJ*12;
    for (int j = 0; j < NJ; j++) {
        const float* Wj = Aw + j*12;
        float jx = J[j*3+0], jy = J[j*3+1], jz = J[j*3+2];
#pragma unroll
        for (int r = 0; r < 3; r++) {
            Ab[j*12 + r*4 + 0] = Wj[r*3+0];
            Ab[j*12 + r*4 + 1] = Wj[r*3+1];
            Ab[j*12 + r*4 + 2] = Wj[r*3+2];
            Ab[j*12 + r*4 + 3] = Wj[9+r] - (Wj[r*3+0]*jx + Wj[r*3+1]*jy + Wj[r*3+2]*jz);
        }
    }
}

// ---------------------------------------------------------------------------
// K4a: v_posed GEMM  C[b][vc] = sum_k F[k][b] * P[k][vc]
//   Block tile 128b x 128vc, 256 threads, thread tile 8b x 8vc (8x4 f32x2).
//   cp.async double-buffered; K = 224 (padded, branch-free staging).
// ---------------------------------------------------------------------------
#define GK 16
#define NKC (KP/GK)   // 14

__global__ __launch_bounds__(256, 2) void k4a_gemm() {
    __shared__ __align__(16) float sP[2][GK*128];   // 16KB
    __shared__ __align__(16) float sF[2][GK*256];   // 32KB
    int tid = threadIdx.x;
    int tx = tid & 15;      // vc octet 0..15
    int ty = tid >> 4;      // batch octet 0..15
    int n0 = blockIdx.x * 128;
    int b0 = blockIdx.y * 128;

    uint32_t spP0 = (uint32_t)__cvta_generic_to_shared(&sP[0][0]);
    uint32_t spF0 = (uint32_t)__cvta_generic_to_shared(&sF[0][0]);

    ull acc[8][4];
#pragma unroll
    for (int bi = 0; bi < 8; bi++)
#pragma unroll
        for (int ni = 0; ni < 4; ni++) acc[bi][ni] = 0ull;

    // staging lambda
    auto stage = [&](int kc, int s) {
        uint32_t pb = spP0 + s*(GK*128*4);
        uint32_t fb = spF0 + s*(GK*256*4);
#pragma unroll
        for (int r = 0; r < 2; r++) {
            int i = tid + r*256;             // 0..511 float4s of sP
            int row = i >> 5, c4 = i & 31;
            cpasync16(pb + (row*128 + c4*4)*4,
                      &g_P[(size_t)(kc*GK + row)*VCP + n0 + c4*4]);
        }
#pragma unroll
        for (int r = 0; r < 4; r++) {
            int i = tid + r*256;             // 0..1023 float4s of sF
            int row = i >> 6, c4 = i & 63;
            cpasync16(fb + (row*256 + c4*4)*4,
                      &g_pft2[(kc*GK + row)*1024 + b0*2 + c4*4]);
        }
        asm volatile("cp.async.commit_group;");
    };

    stage(0, 0);
    for (int kc = 0; kc < NKC; kc++) {
        int s = kc & 1;
        if (kc + 1 < NKC) stage(kc + 1, s ^ 1);
        else asm volatile("cp.async.commit_group;");  // empty group keeps wait uniform
        asm volatile("cp.async.wait_group 1;");
        __syncthreads();
        const float* Pb = &sP[s][0];
        const float* Fb = &sF[s][0];
#pragma unroll
        for (int kk = 0; kk < GK; kk++) {
            ulonglong2 p0 = *(const ulonglong2*)&Pb[kk*128 + tx*8];
            ulonglong2 p1 = *(const ulonglong2*)&Pb[kk*128 + tx*8 + 4];
            ull a0 = p0.x, a1 = p0.y, a2 = p1.x, a3 = p1.y;
            ull f[8];
#pragma unroll
            for (int q = 0; q < 4; q++) {
                ulonglong2 t = *(const ulonglong2*)&Fb[kk*256 + ty*16 + q*4];
                f[q*2] = t.x; f[q*2+1] = t.y;
            }
#pragma unroll
            for (int bi = 0; bi < 8; bi++) {
                ffma2(acc[bi][0], f[bi], a0);
                ffma2(acc[bi][1], f[bi], a1);
                ffma2(acc[bi][2], f[bi], a2);
                ffma2(acc[bi][3], f[bi], a3);
            }
        }
        __syncthreads();
    }
#pragma unroll
    for (int bi = 0; bi < 8; bi++) {
        float* dst = &g_vposed[(size_t)(b0 + ty*8 + bi)*VCP + n0 + tx*8];
        ulonglong2 s0; s0.x = acc[bi][0]; s0.y = acc[bi][1];
        *(ulonglong2*)dst = s0;
        ulonglong2 s1; s1.x = acc[bi][2]; s1.y = acc[bi][3];
        *(ulonglong2*)(dst + 4) = s1;
    }
}

// ---------------------------------------------------------------------------
// K4b: skinning. Block tile: 16 batches (8 f32x2 pairs) x 64 verts.
// ---------------------------------------------------------------------------
#define ST_VT 64
#define ST_BT 16

__global__ __launch_bounds__(256) void k4b_skin(
    const float* __restrict__ lbs, float* __restrict__ out)
{
    __shared__ __align__(16) float sA2[8*288*2];  // 18KB pair-interleaved
    __shared__ float sW[ST_VT*25];                 // stride 25: conflict-free
    int tid = threadIdx.x;
    int v0 = blockIdx.x * ST_VT;
    int b0 = blockIdx.y * ST_BT;

    for (int i = tid; i < 8*2*288; i += 256) {
        int p = i / 576; int rem = i % 576; int h = rem / 288; int r = rem % 288;
        sA2[(p*288 + r)*2 + h] = g_A[(size_t)(b0 + 2*p + h)*288 + r];
    }
    for (int i = tid; i < ST_VT*NJ; i += 256) {
        int vl = i / NJ; int j = i % NJ;
        int v = v0 + vl;
        sW[vl*25 + j] = (v < V) ? lbs[v*NJ + j] : 0.0f;
    }
    __syncthreads();

    int p  = tid >> 5;
    int vt = tid & 31;

    ull T[2][12];
#pragma unroll
    for (int vi = 0; vi < 2; vi++)
#pragma unroll
        for (int e = 0; e < 12; e++) T[vi][e] = 0ull;

    const float* Ap = sA2 + p*576;
#pragma unroll
    for (int j = 0; j < NJ; j++) {
        ull a[12];
#pragma unroll
        for (int e2 = 0; e2 < 6; e2++) {
            ulonglong2 t = *(ulonglong2*)&Ap[(j*12 + e2*2)*2];
            a[e2*2] = t.x; a[e2*2+1] = t.y;
        }
#pragma unroll
        for (int vi = 0; vi < 2; vi++) {
            float w = sW[(vt + vi*32)*25 + j];
            ull ww = pack2(w, w);
#pragma unroll
            for (int e = 0; e < 12; e++) ffma2(T[vi][e], ww, a[e]);
        }
    }

#pragma unroll
    for (int vi = 0; vi < 2; vi++) {
        int v = v0 + vt + vi*32;
        if (v >= V) continue;
        float Ta[12], Tb[12];
#pragma unroll
        for (int e = 0; e < 12; e++) unpack2(T[vi][e], Ta[e], Tb[e]);
        {
            int b = b0 + 2*p;
            const float* hp = &g_vposed[(size_t)b*VCP + v*3];
            float vx = hp[0], vy = hp[1], vz = hp[2];
            float* o = out + VERT_OFF + ((size_t)b*V + v)*3;
            o[0] = Ta[0]*vx + Ta[1]*vy + Ta[2]*vz  + Ta[3];
            o[1] = Ta[4]*vx + Ta[5]*vy + Ta[6]*vz  + Ta[7];
            o[2] = Ta[8]*vx + Ta[9]*vy + Ta[10]*vz + Ta[11];
        }
        {
            int b = b0 + 2*p + 1;
            const float* hp = &g_vposed[(size_t)b*VCP + v*3];
            float vx = hp[0], vy = hp[1], vz = hp[2];
            float* o = out + VERT_OFF + ((size_t)b*V + v)*3;
            o[0] = Tb[0]*vx + Tb[1]*vy + Tb[2]*vz  + Tb[3];
            o[1] = Tb[4]*vx + Tb[5]*vy + Tb[6]*vz  + Tb[7];
            o[2] = Tb[8]*vx + Tb[9]*vy + Tb[10]*vz + Tb[11];
        }
    }
}

// ---------------------------------------------------------------------------
// K5: joints = regressor^T @ vertices — 2 batches per block (shared sreg tile)
// ---------------------------------------------------------------------------
__global__ __launch_bounds__(256) void k5_joints(const float* __restrict__ jreg,
                                                 float* __restrict__ out)
{
    __shared__ float sreg[128*NJO];          // 9.5KB
    __shared__ float spart[2][4][NJO*3];
    int tid = threadIdx.x;
    int half = tid >> 7, t = tid & 127;
    int b = blockIdx.x*2 + half;
    const float* verts = out + VERT_OFF + (size_t)b*V*3;
    float acc[NJO*3];
#pragma unroll
    for (int e = 0; e < NJO*3; e++) acc[e] = 0.0f;

    for (int base = 0; base < V; base += 128) {
        for (int i = tid; i < 128*NJO; i += 256) {
            int row = base + i / NJO;
            sreg[i] = (row < V) ? jreg[row*NJO + (i % NJO)] : 0.0f;
        }
        __syncthreads();
        int v = base + t;
        if (v < V) {
            float px = verts[v*3+0], py = verts[v*3+1], pz = verts[v*3+2];
#pragma unroll
            for (int j = 0; j < NJO; j++) {
                float r = sreg[t*NJO + j];
                acc[j*3+0] += r*px;
                acc[j*3+1] += r*py;
                acc[j*3+2] += r*pz;
            }
        }
        __syncthreads();
    }
#pragma unroll
    for (int e = 0; e < NJO*3; e++) {
#pragma unroll
        for (int o = 16; o > 0; o >>= 1)
            acc[e] += __shfl_down_sync(0xffffffffu, acc[e], o);
    }
    int warp = (tid >> 5) & 3, lane = tid & 31;
    if (lane == 0) {
#pragma unroll
        for (int e = 0; e < NJO*3; e++) spart[half][warp][e] = acc[e];
    }
    __syncthreads();
    if (t < NJO*3) {
        float s = spart[half][0][t] + spart[half][1][t]
                + spart[half][2][t] + spart[half][3][t];
        out[JNT_OFF + b*(NJO*3) + t] = s;
    }
}

// ---------------------------------------------------------------------------
extern "C" void kernel_launch(void* const* d_in, const int* in_sizes, int n_in,
                              void* d_out, int out_size) {
    const float* inputs     = (const float*)d_in[0];
    const float* v_template = (const float*)d_in[1];
    const float* shapes     = (const float*)d_in[2];
    const float* posedirs   = (const float*)d_in[3];
    const float* smpl_reg   = (const float*)d_in[4];
    const float* lbs        = (const float*)d_in[5];
    const float* jreg       = (const float*)d_in[6];
    float* out = (float*)d_out;

    k0_pack<<<(KP*(VCP/4) + 255)/256, 256>>>(posedirs, shapes, v_template);
    k1_rodrigues<<<(NJ*B + 255)/256, 256>>>(inputs, out);
    k2_jdirs<<<33, 256>>>(v_template, shapes, smpl_reg);
    k3_chain<<<B/32, 32>>>(inputs, out);
    dim3 ga(VCP/128, B/128);                    // (162, 4)
    k4a_gemm<<<ga, 256>>>();
    dim3 gb((V + ST_VT - 1)/ST_VT, B/ST_BT);    // (108, 32)
    k4b_skin<<<gb, 256>>>(lbs, out);
    k5_joints<<<B/2, 256>>>(jreg, out);
}

// round 13
// speedup vs baseline: 3.0748x; 1.0517x over previous
#include <cuda_runtime.h>
#include <cstdint>

#define B 512
#define V 6890
#define NJ 24
#define NP 207
#define NJO 19
#define VC (V*3)            // 20670
#define VCP 20736           // padded vc stride = 162*128
#define KP 224              // padded K (218 real rows)

#define VERT_OFF 0
#define JNT_OFF  (B*V*3)              // 10583040
#define ROT_OFF  (JNT_OFF + B*NJO*3)  // 10612224

typedef unsigned long long ull;

// Scratch (__device__ globals: allocation-free rule)
__device__ float g_P[(size_t)KP*VCP];     // 18.6MB packed+padded [posedirs;shapes;template;0]
__device__ float g_pft2[KP*1024];         // [k][b*2+{0,1}] duplicated factor matrix
__device__ float g_Jdirs[11*NJ*3];
__device__ float g_A[B*NJ*12];            // relative transforms 3x4 row-major
__device__ float g_vposed[(size_t)B*VCP]; // 42.5MB v_posed (incl template)

// ---- packed f32x2 helpers --------------------------------------------------
__device__ __forceinline__ void ffma2(ull &d, ull a, ull b) {
    asm("fma.rn.f32x2 %0, %1, %2, %0;" : "+l"(d) : "l"(a), "l"(b));
}
__device__ __forceinline__ ull pack2(float x, float y) {
    ull r; asm("mov.b64 %0, {%1, %2};" : "=l"(r) : "f"(x), "f"(y)); return r;
}
__device__ __forceinline__ void unpack2(ull v, float &lo, float &hi) {
    asm("mov.b64 {%0, %1}, %2;" : "=f"(lo), "=f"(hi) : "l"(v));
}
__device__ __forceinline__ void cpasync16(uint32_t s, const void* g) {
    asm volatile("cp.async.cg.shared.global [%0], [%1], 16;" :: "r"(s), "l"(g));
}

// ---------------------------------------------------------------------------
// K0: pack P = [posedirs; shapes; v_template; zeros] into padded g_P
// ---------------------------------------------------------------------------
__global__ void k0_pack(const float* __restrict__ posedirs,
                        const float* __restrict__ shapes,
                        const float* __restrict__ v_template) {
    int idx = blockIdx.x * blockDim.x + threadIdx.x;   // one float4 of g_P
    if (idx >= KP*(VCP/4)) return;
    int k = idx / (VCP/4);
    int q = idx % (VCP/4);
    int gc = q * 4;
    float4 val = make_float4(0.f, 0.f, 0.f, 0.f);
    if (k < 218) {
        const float* src = (k < NP) ? posedirs + (size_t)k*VC
                         : (k < 217) ? shapes + (size_t)(k-NP)*VC
                         : v_template;
        if (gc + 3 < VC) {
            float2 u = *(const float2*)(src + gc);
            float2 w = *(const float2*)(src + gc + 2);
            val.x = u.x; val.y = u.y; val.z = w.x; val.w = w.y;
        } else {
            if (gc + 0 < VC) val.x = src[gc + 0];
            if (gc + 1 < VC) val.y = src[gc + 1];
            if (gc + 2 < VC) val.z = src[gc + 2];
        }
    }
    *(float4*)&g_P[(size_t)k*VCP + gc] = val;
}

// ---------------------------------------------------------------------------
// K1: Rodrigues -> rot output + duplicated factor matrix g_pft2
// ---------------------------------------------------------------------------
__global__ void k1_rodrigues(const float* __restrict__ inputs, float* __restrict__ out) {
    int g = blockIdx.x * blockDim.x + threadIdx.x;
    if (g >= NJ * B) return;
    int j = g / B;
    int b = g % B;
    float rx = inputs[b*82 + j*3 + 0];
    float ry = inputs[b*82 + j*3 + 1];
    float rz = inputs[b*82 + j*3 + 2];
    float ax = rx + 1e-8f, ay = ry + 1e-8f, az = rz + 1e-8f;
    float angle = sqrtf(ax*ax + ay*ay + az*az);
    float inv = 1.0f / angle;
    float nx = rx*inv, ny = ry*inv, nz = rz*inv;
    float c = cosf(angle), s = sinf(angle), oc = 1.0f - c;
    float R[9];
    R[0] = c + oc*nx*nx;    R[1] = oc*nx*ny - s*nz; R[2] = oc*nx*nz + s*ny;
    R[3] = oc*ny*nx + s*nz; R[4] = c + oc*ny*ny;    R[5] = oc*ny*nz - s*nx;
    R[6] = oc*nz*nx - s*ny; R[7] = oc*nz*ny + s*nx; R[8] = c + oc*nz*nz;
    float* ro = out + ROT_OFF + (size_t)b*216 + j*9;
#pragma unroll
    for (int m = 0; m < 9; m++) ro[m] = R[m];
    if (j > 0) {
        int base = (j-1)*9;
#pragma unroll
        for (int m = 0; m < 9; m++) {
            float idm = (m == 0 || m == 4 || m == 8) ? 1.0f : 0.0f;
            float val = R[m] - idm;
            g_pft2[(base + m)*1024 + b*2 + 0] = val;
            g_pft2[(base + m)*1024 + b*2 + 1] = val;
        }
    } else {
#pragma unroll
        for (int k = 0; k < 10; k++) {
            float val = inputs[b*82 + 72 + k];
            g_pft2[(NP + k)*1024 + b*2 + 0] = val;
            g_pft2[(NP + k)*1024 + b*2 + 1] = val;
        }
        g_pft2[217*1024 + b*2 + 0] = 1.0f;
        g_pft2[217*1024 + b*2 + 1] = 1.0f;
#pragma unroll
        for (int k = 218; k < KP; k++) {
            g_pft2[k*1024 + b*2 + 0] = 0.0f;
            g_pft2[k*1024 + b*2 + 1] = 0.0f;
        }
    }
}

// ---------------------------------------------------------------------------
// K2: Jdirs (shape basis + template regressed to joints) — coalesced
// ---------------------------------------------------------------------------
__global__ __launch_bounds__(256) void k2_jdirs(const float* __restrict__ v_template,
                         const float* __restrict__ shapes,
                         const float* __restrict__ smpl_reg) {
    __shared__ float spart[8][NJ];
    int k = blockIdx.x / 3;
    int c = blockIdx.x % 3;
    int tid = threadIdx.x;
    const float* src = (k < 10) ? (shapes + (size_t)k*VC) : v_template;
    float acc[NJ];
#pragma unroll
    for (int j = 0; j < NJ; j++) acc[j] = 0.0f;
    for (int v = tid; v < V; v += 256) {
        float sv = src[v*3 + c];
        const float4* r = (const float4*)&smpl_reg[v*NJ];
#pragma unroll
        for (int q = 0; q < 6; q++) {
            float4 rv = r[q];
            acc[q*4+0] += sv * rv.x;
            acc[q*4+1] += sv * rv.y;
            acc[q*4+2] += sv * rv.z;
            acc[q*4+3] += sv * rv.w;
        }
    }
#pragma unroll
    for (int j = 0; j < NJ; j++) {
#pragma unroll
        for (int o = 16; o > 0; o >>= 1)
            acc[j] += __shfl_down_sync(0xffffffffu, acc[j], o);
    }
    int warp = tid >> 5, lane = tid & 31;
    if (lane == 0) {
#pragma unroll
        for (int j = 0; j < NJ; j++) spart[warp][j] = acc[j];
    }
    __syncthreads();
    if (tid < NJ) {
        float s = 0.0f;
#pragma unroll
        for (int w = 0; w < 8; w++) s += spart[w][tid];
        g_Jdirs[k*(NJ*3) + tid*3 + c] = s;
    }
}

// ---------------------------------------------------------------------------
// K3: per-batch kinematic chain -> g_A
//   Transposed smem layout sAw[e*33 + t]: bank (e+t)%32 => conflict-free both
//   for per-thread element access and for the coalesced copy-out.
//   Chain fully unrolled with compile-time parents; J in registers.
// ---------------------------------------------------------------------------
__global__ __launch_bounds__(32) void k3_chain(const float* __restrict__ inputs,
                                               const float* __restrict__ out) {
    __shared__ float sJd[11*72];       // 3.2KB staged Jdirs
    __shared__ float sAw[288*33];      // 38KB  [e][t] padded
    int t = threadIdx.x;
    int b = blockIdx.x * 32 + t;

    for (int i = t; i < 11*72; i += 32) sJd[i] = g_Jdirs[i];
    __syncwarp();

    float beta[10];
#pragma unroll
    for (int k = 0; k < 10; k++) beta[k] = inputs[b*82 + 72 + k];

    float J[72];
#pragma unroll
    for (int e = 0; e < 72; e++) {
        float a = sJd[10*72 + e];
#pragma unroll
        for (int k = 0; k < 10; k++) a += beta[k]*sJd[k*72 + e];
        J[e] = a;
    }

    const float* rot = out + ROT_OFF + (size_t)b*216;

    // joint 0: world = [R0 | J0]
#pragma unroll
    for (int m = 0; m < 9; m++) sAw[m*33 + t] = rot[m];
    sAw[ 9*33 + t] = J[0];
    sAw[10*33 + t] = J[1];
    sAw[11*33 + t] = J[2];

    const int parents[NJ] = {0,0,0,0,1,2,3,4,5,6,7,8,9,9,9,12,13,14,16,17,18,19,20,21};
#pragma unroll
    for (int j = 1; j < NJ; j++) {
        const int p = parents[j];
        float Rl[9];
#pragma unroll
        for (int m = 0; m < 9; m++) Rl[m] = rot[j*9 + m];
        float Rp[12];
#pragma unroll
        for (int e = 0; e < 12; e++) Rp[e] = sAw[(p*12 + e)*33 + t];
        float W[12];
#pragma unroll
        for (int r = 0; r < 3; r++)
#pragma unroll
            for (int cc = 0; cc < 3; cc++)
                W[r*3+cc] = Rp[r*3+0]*Rl[0*3+cc] + Rp[r*3+1]*Rl[1*3+cc] + Rp[r*3+2]*Rl[2*3+cc];
        float dx = J[j*3+0]-J[p*3+0], dy = J[j*3+1]-J[p*3+1], dz = J[j*3+2]-J[p*3+2];
#pragma unroll
        for (int r = 0; r < 3; r++)
            W[9+r] = Rp[r*3+0]*dx + Rp[r*3+1]*dy + Rp[r*3+2]*dz + Rp[9+r];
#pragma unroll
        for (int e = 0; e < 12; e++) sAw[(j*12 + e)*33 + t] = W[e];
    }

    // in-place convert world -> relative 3x4 rows
#pragma unroll
    for (int j = 0; j < NJ; j++) {
        float W[12];
#pragma unroll
        for (int e = 0; e < 12; e++) W[e] = sAw[(j*12 + e)*33 + t];
        float jx = J[j*3+0], jy = J[j*3+1], jz = J[j*3+2];
        float Ar[12];
#pragma unroll
        for (int r = 0; r < 3; r++) {
            Ar[r*4+0] = W[r*3+0];
            Ar[r*4+1] = W[r*3+1];
            Ar[r*4+2] = W[r*3+2];
            Ar[r*4+3] = W[9+r] - (W[r*3+0]*jx + W[r*3+1]*jy + W[r*3+2]*jz);
        }
#pragma unroll
        for (int e = 0; e < 12; e++) sAw[(j*12 + e)*33 + t] = Ar[e];
    }
    __syncwarp();

    // coalesced copy-out
    size_t base = (size_t)(blockIdx.x*32) * 288;
    for (int idx = t; idx < 32*288; idx += 32) {
        int bb = idx / 288, e = idx % 288;
        g_A[base + idx] = sAw[e*33 + bb];
    }
}

// ---------------------------------------------------------------------------
// K4a: v_posed GEMM  C[b][vc] = sum_k F[k][b] * P[k][vc]
// ---------------------------------------------------------------------------
#define GK 16
#define NKC (KP/GK)   // 14

__global__ __launch_bounds__(256, 2) void k4a_gemm() {
    __shared__ __align__(16) float sP[2][GK*128];   // 16KB
    __shared__ __align__(16) float sF[2][GK*256];   // 32KB
    int tid = threadIdx.x;
    int tx = tid & 15;      // vc octet 0..15
    int ty = tid >> 4;      // batch octet 0..15
    int n0 = blockIdx.x * 128;
    int b0 = blockIdx.y * 128;

    uint32_t spP0 = (uint32_t)__cvta_generic_to_shared(&sP[0][0]);
    uint32_t spF0 = (uint32_t)__cvta_generic_to_shared(&sF[0][0]);

    ull acc[8][4];
#pragma unroll
    for (int bi = 0; bi < 8; bi++)
#pragma unroll
        for (int ni = 0; ni < 4; ni++) acc[bi][ni] = 0ull;

    auto stage = [&](int kc, int s) {
        uint32_t pb = spP0 + s*(GK*128*4);
        uint32_t fb = spF0 + s*(GK*256*4);
#pragma unroll
        for (int r = 0; r < 2; r++) {
            int i = tid + r*256;
            int row = i >> 5, c4 = i & 31;
            cpasync16(pb + (row*128 + c4*4)*4,
                      &g_P[(size_t)(kc*GK + row)*VCP + n0 + c4*4]);
        }
#pragma unroll
        for (int r = 0; r < 4; r++) {
            int i = tid + r*256;
            int row = i >> 6, c4 = i & 63;
            cpasync16(fb + (row*256 + c4*4)*4,
                      &g_pft2[(kc*GK + row)*1024 + b0*2 + c4*4]);
        }
        asm volatile("cp.async.commit_group;");
    };

    stage(0, 0);
    for (int kc = 0; kc < NKC; kc++) {
        int s = kc & 1;
        if (kc + 1 < NKC) stage(kc + 1, s ^ 1);
        else asm volatile("cp.async.commit_group;");
        asm volatile("cp.async.wait_group 1;");
        __syncthreads();
        const float* Pb = &sP[s][0];
        const float* Fb = &sF[s][0];
#pragma unroll
        for (int kk = 0; kk < GK; kk++) {
            ulonglong2 p0 = *(const ulonglong2*)&Pb[kk*128 + tx*8];
            ulonglong2 p1 = *(const ulonglong2*)&Pb[kk*128 + tx*8 + 4];
            ull a0 = p0.x, a1 = p0.y, a2 = p1.x, a3 = p1.y;
            ull f[8];
#pragma unroll
            for (int q = 0; q < 4; q++) {
                ulonglong2 tq = *(const ulonglong2*)&Fb[kk*256 + ty*16 + q*4];
                f[q*2] = tq.x; f[q*2+1] = tq.y;
            }
#pragma unroll
            for (int bi = 0; bi < 8; bi++) {
                ffma2(acc[bi][0], f[bi], a0);
                ffma2(acc[bi][1], f[bi], a1);
                ffma2(acc[bi][2], f[bi], a2);
                ffma2(acc[bi][3], f[bi], a3);
            }
        }
        __syncthreads();
    }
#pragma unroll
    for (int bi = 0; bi < 8; bi++) {
        float* dst = &g_vposed[(size_t)(b0 + ty*8 + bi)*VCP + n0 + tx*8];
        ulonglong2 s0; s0.x = acc[bi][0]; s0.y = acc[bi][1];
        *(ulonglong2*)dst = s0;
        ulonglong2 s1; s1.x = acc[bi][2]; s1.y = acc[bi][3];
        *(ulonglong2*)(dst + 4) = s1;
    }
}

// ---------------------------------------------------------------------------
// K4b: skinning. Block tile: 16 batches (8 f32x2 pairs) x 64 verts.
// ---------------------------------------------------------------------------
#define ST_VT 64
#define ST_BT 16

__global__ __launch_bounds__(256) void k4b_skin(
    const float* __restrict__ lbs, float* __restrict__ out)
{
    __shared__ __align__(16) float sA2[8*288*2];  // 18KB pair-interleaved
    __shared__ float sW[ST_VT*25];
    int tid = threadIdx.x;
    int v0 = blockIdx.x * ST_VT;
    int b0 = blockIdx.y * ST_BT;

    for (int i = tid; i < 8*2*288; i += 256) {
        int p = i / 576; int rem = i % 576; int h = rem / 288; int r = rem % 288;
        sA2[(p*288 + r)*2 + h] = g_A[(size_t)(b0 + 2*p + h)*288 + r];
    }
    for (int i = tid; i < ST_VT*NJ; i += 256) {
        int vl = i / NJ; int j = i % NJ;
        int v = v0 + vl;
        sW[vl*25 + j] = (v < V) ? lbs[v*NJ + j] : 0.0f;
    }
    __syncthreads();

    int p  = tid >> 5;
    int vt = tid & 31;

    ull T[2][12];
#pragma unroll
    for (int vi = 0; vi < 2; vi++)
#pragma unroll
        for (int e = 0; e < 12; e++) T[vi][e] = 0ull;

    const float* Ap = sA2 + p*576;
#pragma unroll
    for (int j = 0; j < NJ; j++) {
        ull a[12];
#pragma unroll
        for (int e2 = 0; e2 < 6; e2++) {
            ulonglong2 t = *(ulonglong2*)&Ap[(j*12 + e2*2)*2];
            a[e2*2] = t.x; a[e2*2+1] = t.y;
        }
#pragma unroll
        for (int vi = 0; vi < 2; vi++) {
            float w = sW[(vt + vi*32)*25 + j];
            ull ww = pack2(w, w);
#pragma unroll
            for (int e = 0; e < 12; e++) ffma2(T[vi][e], ww, a[e]);
        }
    }

#pragma unroll
    for (int vi = 0; vi < 2; vi++) {
        int v = v0 + vt + vi*32;
        if (v >= V) continue;
        float Ta[12], Tb[12];
#pragma unroll
        for (int e = 0; e < 12; e++) unpack2(T[vi][e], Ta[e], Tb[e]);
        {
            int b = b0 + 2*p;
            const float* hp = &g_vposed[(size_t)b*VCP + v*3];
            float vx = hp[0], vy = hp[1], vz = hp[2];
            float* o = out + VERT_OFF + ((size_t)b*V + v)*3;
            o[0] = Ta[0]*vx + Ta[1]*vy + Ta[2]*vz  + Ta[3];
            o[1] = Ta[4]*vx + Ta[5]*vy + Ta[6]*vz  + Ta[7];
            o[2] = Ta[8]*vx + Ta[9]*vy + Ta[10]*vz + Ta[11];
        }
        {
            int b = b0 + 2*p + 1;
            const float* hp = &g_vposed[(size_t)b*VCP + v*3];
            float vx = hp[0], vy = hp[1], vz = hp[2];
            float* o = out + VERT_OFF + ((size_t)b*V + v)*3;
            o[0] = Tb[0]*vx + Tb[1]*vy + Tb[2]*vz  + Tb[3];
            o[1] = Tb[4]*vx + Tb[5]*vy + Tb[6]*vz  + Tb[7];
            o[2] = Tb[8]*vx + Tb[9]*vy + Tb[10]*vz + Tb[11];
        }
    }
}

// ---------------------------------------------------------------------------
// K5: joints = regressor^T @ vertices — 8 batches per block (one per warp),
//     shared 128-row jreg tile (stride 21: conflict-free).
// ---------------------------------------------------------------------------
__global__ __launch_bounds__(256) void k5_joints(const float* __restrict__ jreg,
                                                 float* __restrict__ out)
{
    __shared__ float sreg[128*21];   // 10.8KB
    int tid = threadIdx.x;
    int warp = tid >> 5, lane = tid & 31;
    int b = blockIdx.x*8 + warp;
    const float* verts = out + VERT_OFF + (size_t)b*V*3;
    float acc[NJO*3];
#pragma unroll
    for (int e = 0; e < NJO*3; e++) acc[e] = 0.0f;

    for (int base = 0; base < V; base += 128) {
        __syncthreads();
        for (int i = tid; i < 128*NJO; i += 256) {
            int rr = i / NJO, j = i % NJO;
            int row = base + rr;
            sreg[rr*21 + j] = (row < V) ? jreg[row*NJO + j] : 0.0f;
        }
        __syncthreads();
#pragma unroll
        for (int vv = 0; vv < 4; vv++) {
            int vl = vv*32 + lane;
            int v = base + vl;
            if (v < V) {
                float px = verts[v*3+0], py = verts[v*3+1], pz = verts[v*3+2];
#pragma unroll
                for (int j = 0; j < NJO; j++) {
                    float r = sreg[vl*21 + j];
                    acc[j*3+0] += r*px;
                    acc[j*3+1] += r*py;
                    acc[j*3+2] += r*pz;
                }
            }
        }
    }
#pragma unroll
    for (int e = 0; e < NJO*3; e++) {
#pragma unroll
        for (int o = 16; o > 0; o >>= 1)
            acc[e] += __shfl_down_sync(0xffffffffu, acc[e], o);
    }
    if (lane == 0) {
#pragma unroll
        for (int e = 0; e < NJO*3; e++)
            out[JNT_OFF + b*(NJO*3) + e] = acc[e];
    }
}

// ---------------------------------------------------------------------------
extern "C" void kernel_launch(void* const* d_in, const int* in_sizes, int n_in,
                              void* d_out, int out_size) {
    const float* inputs     = (const float*)d_in[0];
    const float* v_template = (const float*)d_in[1];
    const float* shapes     = (const float*)d_in[2];
    const float* posedirs   = (const float*)d_in[3];
    const float* smpl_reg   = (const float*)d_in[4];
    const float* lbs        = (const float*)d_in[5];
    const float* jreg       = (const float*)d_in[6];
    float* out = (float*)d_out;

    k0_pack<<<(KP*(VCP/4) + 255)/256, 256>>>(posedirs, shapes, v_template);
    k1_rodrigues<<<(NJ*B + 255)/256, 256>>>(inputs, out);
    k2_jdirs<<<33, 256>>>(v_template, shapes, smpl_reg);
    k3_chain<<<B/32, 32>>>(inputs, out);
    dim3 ga(VCP/128, B/128);                    // (162, 4)
    k4a_gemm<<<ga, 256>>>();
    dim3 gb((V + ST_VT - 1)/ST_VT, B/ST_BT);    // (108, 32)
    k4b_skin<<<gb, 256>>>(lbs, out);
    k5_joints<<<B/8, 256>>>(jreg, out);
}